// round 5
// baseline (speedup 1.0000x reference)
#include <cuda_runtime.h>
#include <cuda_bf16.h>

// Scratch (no allocation allowed).
__device__ double             g_sums[3];
__device__ unsigned long long g_cnts[3];
__device__ float              g_means[3];

// ---------------------------------------------------------------------------
// Kernel 0: zero accumulators (graph replays reuse them).
// ---------------------------------------------------------------------------
__global__ void iwap_zero_kernel() {
    int i = threadIdx.x;
    if (i < 3) {
        g_sums[i]  = 0.0;
        g_cnts[i]  = 0ull;
        g_means[i] = 0.0f;
    }
}

// ---------------------------------------------------------------------------
// Kernel 1: grid-stride reduction (unchanged — single wave, ~5.3TB/s).
// Only class 0/1 accumulated explicitly; class 2 derived from totals.
// ---------------------------------------------------------------------------
__global__ __launch_bounds__(256)
void iwap_reduce_kernel(const float4* __restrict__ feats4,
                        const int4*  __restrict__ inst4,
                        const float* __restrict__ feats,
                        const int*   __restrict__ inst,
                        int nitems, int npix) {
    float    ptot = 0.f, s0 = 0.f, s1 = 0.f;
    unsigned c0 = 0, c1 = 0, nit = 0;

    const int stride = gridDim.x * blockDim.x;
    for (int i = blockIdx.x * blockDim.x + threadIdx.x; i < nitems; i += stride) {
        int4   cls = __ldg(&inst4[i]);
        float4 a   = __ldcs(&feats4[3 * i + 0]);
        float4 b   = __ldcs(&feats4[3 * i + 1]);
        float4 d   = __ldcs(&feats4[3 * i + 2]);
        float p0 = a.x + a.y + a.z;
        float p1 = a.w + b.x + b.y;
        float p2 = b.z + b.w + d.x;
        float p3 = d.y + d.z + d.w;
        ptot += (p0 + p1) + (p2 + p3);
        s0 += (cls.x == 0) ? p0 : 0.f;  c0 += (cls.x == 0);
        s1 += (cls.x == 1) ? p0 : 0.f;  c1 += (cls.x == 1);
        s0 += (cls.y == 0) ? p1 : 0.f;  c0 += (cls.y == 0);
        s1 += (cls.y == 1) ? p1 : 0.f;  c1 += (cls.y == 1);
        s0 += (cls.z == 0) ? p2 : 0.f;  c0 += (cls.z == 0);
        s1 += (cls.z == 1) ? p2 : 0.f;  c1 += (cls.z == 1);
        s0 += (cls.w == 0) ? p3 : 0.f;  c0 += (cls.w == 0);
        s1 += (cls.w == 1) ? p3 : 0.f;  c1 += (cls.w == 1);
        nit++;
    }

    unsigned ntail = 0;
    if (blockIdx.x == 0 && threadIdx.x == 0) {
        for (int p = nitems * 4; p < npix; p++) {
            int   c  = inst[p];
            float ps = feats[3 * p] + feats[3 * p + 1] + feats[3 * p + 2];
            ptot += ps; ntail++;
            if      (c == 0) { s0 += ps; c0++; }
            else if (c == 1) { s1 += ps; c1++; }
        }
    }

    float    s2 = ptot - s0 - s1;
    unsigned c2 = 4u * nit + ntail - c0 - c1;

    #pragma unroll
    for (int off = 16; off > 0; off >>= 1) {
        s0 += __shfl_down_sync(0xffffffffu, s0, off);
        s1 += __shfl_down_sync(0xffffffffu, s1, off);
        s2 += __shfl_down_sync(0xffffffffu, s2, off);
        c0 += __shfl_down_sync(0xffffffffu, c0, off);
        c1 += __shfl_down_sync(0xffffffffu, c1, off);
        c2 += __shfl_down_sync(0xffffffffu, c2, off);
    }

    __shared__ float    bs[3];
    __shared__ unsigned bc[3];
    if (threadIdx.x < 3) { bs[threadIdx.x] = 0.f; bc[threadIdx.x] = 0u; }
    __syncthreads();
    if ((threadIdx.x & 31) == 0) {
        atomicAdd(&bs[0], s0); atomicAdd(&bs[1], s1); atomicAdd(&bs[2], s2);
        atomicAdd(&bc[0], c0); atomicAdd(&bc[1], c1); atomicAdd(&bc[2], c2);
    }
    __syncthreads();
    if (threadIdx.x < 3) {
        atomicAdd(&g_sums[threadIdx.x], (double)bs[threadIdx.x]);
        atomicAdd(&g_cnts[threadIdx.x], (unsigned long long)bc[threadIdx.x]);
    }
}

// ---------------------------------------------------------------------------
// Kernel 2: finalize means. Count includes the 3 channels (x3).
// ---------------------------------------------------------------------------
__global__ void iwap_finalize_kernel() {
    int c = threadIdx.x;
    if (c < 3) {
        double cnt = 3.0 * (double)g_cnts[c];
        g_means[c] = (cnt > 0.0) ? (float)(g_sums[c] / cnt) : 0.0f;
    }
}

// ---------------------------------------------------------------------------
// Kernel 3: BARRIER-FREE output-mapped scatter. Thread owns output float4 j
// (lane-contiguous -> coalesced STG.128, no smem, no __syncthreads anywhere).
// Vector j covers floats 4j..4j+3 = end of pixel p=4j/3 and start of p+1;
// split pattern depends only on j%3:
//   0 -> [lo,lo,lo,hi]   1 -> [lo,lo,hi,hi]   2 -> [lo,hi,hi,hi]
// inst loads hit L1/L2 (each 128B inst line feeds ~24 output vectors).
// Stores issue continuously -> DRAM write duty cycle should rise.
// ---------------------------------------------------------------------------
__global__ __launch_bounds__(256)
void iwap_scatter_kernel(const int*   __restrict__ inst,
                         float4* __restrict__ out4,
                         const float* __restrict__ feats,
                         float* __restrict__ out,
                         int nvec, int nfloat) {
    const float m0 = g_means[0], m1 = g_means[1], m2 = g_means[2];
    const int stride = gridDim.x * blockDim.x;

    for (int j = blockIdx.x * blockDim.x + threadIdx.x; j < nvec; j += stride) {
        int f0  = 4 * j;
        int p   = f0 / 3;                 // mul-hi const division
        int mod = f0 - 3 * p;             // == j % 3
        int ca  = __ldg(&inst[p]);
        int cb  = __ldg(&inst[p + 1]);    // p+1 <= npix-1 for all j < nvec

        float lo = (ca == 0) ? m0 : ((ca == 1) ? m1 : m2);
        float hi = (cb == 0) ? m0 : ((cb == 1) ? m1 : m2);

        float4 r;
        r.x = lo;
        r.y = (mod == 2) ? hi : lo;
        r.z = (mod == 0) ? lo : hi;
        r.w = hi;

        if (((unsigned)ca >= 3u) | ((unsigned)cb >= 3u)) {
            // Essentially-impossible path: out-of-range class keeps feats.
            float rr[4] = {r.x, r.y, r.z, r.w};
            #pragma unroll
            for (int q = 0; q < 4; q++) {
                int fc = f0 + q;
                int c  = (fc < 3 * (p + 1)) ? ca : cb;
                if ((unsigned)c >= 3u) rr[q] = __ldg(&feats[fc]);
            }
            r = make_float4(rr[0], rr[1], rr[2], rr[3]);
        }

        __stcs(&out4[j], r);
    }

    // Tail floats (nfloat not divisible by 4): block 0, scalar.
    if (blockIdx.x == 0) {
        for (int fc = 4 * nvec + threadIdx.x; fc < nfloat; fc += blockDim.x) {
            int p = fc / 3;
            int c = inst[p];
            float v;
            if ((unsigned)c < 3u) v = (c == 0) ? m0 : ((c == 1) ? m1 : m2);
            else                  v = feats[fc];
            out[fc] = v;
        }
    }
}

// ---------------------------------------------------------------------------
extern "C" void kernel_launch(void* const* d_in, const int* in_sizes, int n_in,
                              void* d_out, int out_size) {
    const float* feats = (const float*)d_in[0];   // [16,1024,1024,3] f32
    const int*   inst  = (const int*)d_in[1];     // [16,1024,1024,1] i32
    float*       out   = (float*)d_out;

    const int npix   = in_sizes[1];               // 16*1024*1024
    const int nitems = npix >> 2;                 // 4 pixels per reduce item
    const int nfloat = npix * 3;                  // output floats
    const int nvec   = nfloat >> 2;               // output float4s

    const float4* feats4 = (const float4*)feats;
    const int4*   inst4  = (const int4*)inst;
    float4*       out4   = (float4*)out;

    iwap_zero_kernel<<<1, 32>>>();

    const int rblocks = 1216;                     // 8 per SM, single wave
    iwap_reduce_kernel<<<rblocks, 256>>>(feats4, inst4, feats, inst, nitems, npix);

    iwap_finalize_kernel<<<1, 32>>>();

    const int sblocks = 1216;                     // persistent, barrier-free
    iwap_scatter_kernel<<<sblocks, 256>>>(inst, out4, feats, out, nvec, nfloat);
}

// round 6
// speedup vs baseline: 1.0411x; 1.0411x over previous
#include <cuda_runtime.h>
#include <cuda_bf16.h>

// Scratch (no allocation allowed).
__device__ double             g_sums[3];
__device__ unsigned long long g_cnts[3];

// ---------------------------------------------------------------------------
// Kernel 0: zero accumulators (graph replays reuse them).
// ---------------------------------------------------------------------------
__global__ void iwap_zero_kernel() {
    int i = threadIdx.x;
    if (i < 3) {
        g_sums[i] = 0.0;
        g_cnts[i] = 0ull;
    }
}

// ---------------------------------------------------------------------------
// Per-item accumulate: 4 pixels (1 int4 + 3 float4).
// ---------------------------------------------------------------------------
__device__ __forceinline__ void acc_item(const int4& cls,
                                         const float4& a, const float4& b,
                                         const float4& d,
                                         float& ptot, float& s0, float& s1,
                                         unsigned& c0, unsigned& c1) {
    float p0 = a.x + a.y + a.z;
    float p1 = a.w + b.x + b.y;
    float p2 = b.z + b.w + d.x;
    float p3 = d.y + d.z + d.w;
    ptot += (p0 + p1) + (p2 + p3);
    s0 += (cls.x == 0) ? p0 : 0.f;  c0 += (cls.x == 0);
    s1 += (cls.x == 1) ? p0 : 0.f;  c1 += (cls.x == 1);
    s0 += (cls.y == 0) ? p1 : 0.f;  c0 += (cls.y == 0);
    s1 += (cls.y == 1) ? p1 : 0.f;  c1 += (cls.y == 1);
    s0 += (cls.z == 0) ? p2 : 0.f;  c0 += (cls.z == 0);
    s1 += (cls.z == 1) ? p2 : 0.f;  c1 += (cls.z == 1);
    s0 += (cls.w == 0) ? p3 : 0.f;  c0 += (cls.w == 0);
    s1 += (cls.w == 1) ? p3 : 0.f;  c1 += (cls.w == 1);
}

// ---------------------------------------------------------------------------
// Kernel 1: grid-stride reduction, 2x unrolled with front-batched loads
// (8 loads in flight before any dependent math -> higher MLP_eff).
// Only class 0/1 accumulated explicitly; class 2 derived from totals.
// feats streamed (evict-first) so inst lines survive in L2 for the scatter.
// ---------------------------------------------------------------------------
__global__ __launch_bounds__(256)
void iwap_reduce_kernel(const float4* __restrict__ feats4,
                        const int4*  __restrict__ inst4,
                        const float* __restrict__ feats,
                        const int*   __restrict__ inst,
                        int nitems, int npix) {
    float    ptot = 0.f, s0 = 0.f, s1 = 0.f;
    unsigned c0 = 0, c1 = 0, nit = 0;

    const int S = gridDim.x * blockDim.x;
    int i = blockIdx.x * blockDim.x + threadIdx.x;

    // 2x unrolled main loop: batch all 8 loads up front.
    for (; i + S < nitems; i += 2 * S) {
        int4   clsA = __ldg(&inst4[i]);
        int4   clsB = __ldg(&inst4[i + S]);
        float4 a0 = __ldcs(&feats4[3 * i + 0]);
        float4 a1 = __ldcs(&feats4[3 * i + 1]);
        float4 a2 = __ldcs(&feats4[3 * i + 2]);
        float4 b0 = __ldcs(&feats4[3 * (i + S) + 0]);
        float4 b1 = __ldcs(&feats4[3 * (i + S) + 1]);
        float4 b2 = __ldcs(&feats4[3 * (i + S) + 2]);
        acc_item(clsA, a0, a1, a2, ptot, s0, s1, c0, c1);
        acc_item(clsB, b0, b1, b2, ptot, s0, s1, c0, c1);
        nit += 2;
    }
    if (i < nitems) {
        int4   cls = __ldg(&inst4[i]);
        float4 a0 = __ldcs(&feats4[3 * i + 0]);
        float4 a1 = __ldcs(&feats4[3 * i + 1]);
        float4 a2 = __ldcs(&feats4[3 * i + 2]);
        acc_item(cls, a0, a1, a2, ptot, s0, s1, c0, c1);
        nit += 1;
    }

    // Tail pixels (npix not divisible by 4) by thread 0 of block 0.
    unsigned ntail = 0;
    if (blockIdx.x == 0 && threadIdx.x == 0) {
        for (int p = nitems * 4; p < npix; p++) {
            int   c  = inst[p];
            float ps = feats[3 * p] + feats[3 * p + 1] + feats[3 * p + 2];
            ptot += ps; ntail++;
            if      (c == 0) { s0 += ps; c0++; }
            else if (c == 1) { s1 += ps; c1++; }
        }
    }

    float    s2 = ptot - s0 - s1;
    unsigned c2 = 4u * nit + ntail - c0 - c1;

    #pragma unroll
    for (int off = 16; off > 0; off >>= 1) {
        s0 += __shfl_down_sync(0xffffffffu, s0, off);
        s1 += __shfl_down_sync(0xffffffffu, s1, off);
        s2 += __shfl_down_sync(0xffffffffu, s2, off);
        c0 += __shfl_down_sync(0xffffffffu, c0, off);
        c1 += __shfl_down_sync(0xffffffffu, c1, off);
        c2 += __shfl_down_sync(0xffffffffu, c2, off);
    }

    __shared__ float    bs[3];
    __shared__ unsigned bc[3];
    if (threadIdx.x < 3) { bs[threadIdx.x] = 0.f; bc[threadIdx.x] = 0u; }
    __syncthreads();
    if ((threadIdx.x & 31) == 0) {
        atomicAdd(&bs[0], s0); atomicAdd(&bs[1], s1); atomicAdd(&bs[2], s2);
        atomicAdd(&bc[0], c0); atomicAdd(&bc[1], c1); atomicAdd(&bc[2], c2);
    }
    __syncthreads();
    if (threadIdx.x < 3) {
        atomicAdd(&g_sums[threadIdx.x], (double)bs[threadIdx.x]);
        atomicAdd(&g_cnts[threadIdx.x], (unsigned long long)bc[threadIdx.x]);
    }
}

// ---------------------------------------------------------------------------
// Kernel 2: scatter, R3 tiled structure (best measured) but with PLAIN
// write-back stores (tests the .cs policy hypothesis) and finalize folded in
// (threads 0-2 compute the class means from g_sums/g_cnts).
// ---------------------------------------------------------------------------
__global__ __launch_bounds__(256)
void iwap_scatter_kernel(const int4*  __restrict__ inst4,
                         float4* __restrict__ out4,
                         const int*   __restrict__ inst,
                         const float* __restrict__ feats,
                         float* __restrict__ out,
                         int npix) {
    __shared__ float vmean[1024];
    __shared__ float smean[3];
    __shared__ int   s_bad;

    const int t        = threadIdx.x;
    const int tileBase = blockIdx.x << 10;           // 1024 pixels per tile

    // Inline finalize: means from the global accumulators (L2-resident).
    if (t < 3) {
        double cnt = 3.0 * (double)g_cnts[t];        // count incl. channels
        smean[t] = (cnt > 0.0) ? (float)(g_sums[t] / cnt) : 0.0f;
    }
    if (t == 0) s_bad = 0;
    __syncthreads();
    const float m0 = smean[0], m1 = smean[1], m2 = smean[2];

    const int tilePix = min(1024, npix - tileBase);

    if (tilePix == 1024) {
        int4 v = __ldg(&inst4[(tileBase >> 2) + t]);
        bool ok = ((unsigned)v.x < 3u) & ((unsigned)v.y < 3u) &
                  ((unsigned)v.z < 3u) & ((unsigned)v.w < 3u);
        if (!ok) s_bad = 1;
        float4 mv;
        mv.x = (v.x == 0) ? m0 : ((v.x == 1) ? m1 : m2);
        mv.y = (v.y == 0) ? m0 : ((v.y == 1) ? m1 : m2);
        mv.z = (v.z == 0) ? m0 : ((v.z == 1) ? m1 : m2);
        mv.w = (v.w == 0) ? m0 : ((v.w == 1) ? m1 : m2);
        *(float4*)&vmean[4 * t] = mv;
        __syncthreads();

        const int j0   = (tileBase >> 2) * 3;        // first float4 of tile
        const int tmod = t % 3;
        #pragma unroll
        for (int k = 0; k < 3; k++) {
            int   idx = (k << 8) + t;                // float4 idx within tile
            int   plo = (4 * idx) / 3;               // low pixel of vector
            int   mod = tmod + k;  mod -= (mod >= 3) ? 3 : 0;
            float lo  = vmean[plo];
            float hi  = vmean[plo + 1];              // plo <= 1022, safe
            float4 r;
            r.x = lo;
            r.y = (mod == 2) ? hi : lo;
            r.z = (mod == 0) ? lo : hi;
            r.w = hi;
            out4[j0 + idx] = r;                      // plain write-back store
        }

        // Essentially-impossible path: out-of-range class keeps feats.
        if (s_bad) {
            __syncthreads();
            for (int q = 0; q < 4; q++) {
                int p = tileBase + 4 * t + q;
                int c = __ldg(&inst[p]);
                if ((unsigned)c >= 3u) {
                    out[3 * p]     = feats[3 * p];
                    out[3 * p + 1] = feats[3 * p + 1];
                    out[3 * p + 2] = feats[3 * p + 2];
                }
            }
        }
    } else {
        // Tail tile: scalar, bounds-checked.
        for (int p = tileBase + t; p < tileBase + tilePix; p += blockDim.x) {
            int c = inst[p];
            if ((unsigned)c < 3u) {
                float m = (c == 0) ? m0 : ((c == 1) ? m1 : m2);
                out[3 * p] = m; out[3 * p + 1] = m; out[3 * p + 2] = m;
            } else {
                out[3 * p]     = feats[3 * p];
                out[3 * p + 1] = feats[3 * p + 1];
                out[3 * p + 2] = feats[3 * p + 2];
            }
        }
    }
}

// ---------------------------------------------------------------------------
extern "C" void kernel_launch(void* const* d_in, const int* in_sizes, int n_in,
                              void* d_out, int out_size) {
    const float* feats = (const float*)d_in[0];   // [16,1024,1024,3] f32
    const int*   inst  = (const int*)d_in[1];     // [16,1024,1024,1] i32
    float*       out   = (float*)d_out;

    const int npix   = in_sizes[1];               // 16*1024*1024
    const int nitems = npix >> 2;                 // 4 pixels per reduce item

    const float4* feats4 = (const float4*)feats;
    const int4*   inst4  = (const int4*)inst;
    float4*       out4   = (float4*)out;

    iwap_zero_kernel<<<1, 32>>>();

    const int rblocks = 1216;                     // 8 per SM, single wave
    iwap_reduce_kernel<<<rblocks, 256>>>(feats4, inst4, feats, inst, nitems, npix);

    const int sblocks = (npix + 1023) / 1024;     // one 1024-pixel tile/block
    iwap_scatter_kernel<<<sblocks, 256>>>(inst4, out4, inst, feats, out, npix);
}